// round 1
// baseline (speedup 1.0000x reference)
#include <cuda_runtime.h>
#include <cuda_bf16.h>

#define NUM_LEVELS 32
#define SCALE_F 0.15f
#define BATCH 8
#define SEQ 8192
#define DIM 1024
#define NTOK (BATCH * SEQ)

// scratch for computed levels (alloc-free rule: __device__ global)
__device__ unsigned char g_levels[NTOK];

// ---------------------------------------------------------------------------
// Kernel A: saturating bracket-depth scan per row.
// f_d(x) = clip(x + d, 0, 31). Family {x -> clip(x+a, l, h)} is closed under
// composition, so we do a Hillis-Steele block scan over (a, l, h) triples.
// One block per batch row, 1024 threads, 8 tokens per thread.
// ---------------------------------------------------------------------------
__global__ __launch_bounds__(1024) void levels_kernel(const int* __restrict__ tok) {
    __shared__ int sa[1024], sl[1024], sh[1024];
    const int b = blockIdx.x;
    const int tid = threadIdx.x;
    const int* __restrict__ row = tok + b * SEQ;
    const int base = tid * 8;

    int d[8];
    // local composite, starting from identity (0, -INF, +INF)
    int a = 0, l = -1000000, h = 1000000;
#pragma unroll
    for (int i = 0; i < 8; i++) {
        int t = row[base + i];
        int di = (int)((t == 40) | (t == 91) | (t == 123))
               - (int)((t == 41) | (t == 93) | (t == 125));
        d[i] = di;
        // compose current with step (di, 0, 31): apply current first, then step
        a += di;
        l = min(max(l + di, 0), NUM_LEVELS - 1);
        h = min(max(h + di, 0), NUM_LEVELS - 1);
    }
    sa[tid] = a; sl[tid] = l; sh[tid] = h;
    __syncthreads();

    // inclusive scan across 1024 threads (10 steps)
    for (int off = 1; off < 1024; off <<= 1) {
        int pa = 0, pl = 0, ph = 0;
        const bool have = (tid >= off);
        if (have) { pa = sa[tid - off]; pl = sl[tid - off]; ph = sh[tid - off]; }
        const int ca = sa[tid], cl = sl[tid], ch = sh[tid];
        __syncthreads();
        if (have) {
            // apply prefix p first, then current c
            sa[tid] = pa + ca;
            sl[tid] = min(max(pl + ca, cl), ch);
            sh[tid] = min(max(ph + ca, cl), ch);
        }
        __syncthreads();
    }

    // exclusive prefix applied to initial level 0
    int x = 0;
    if (tid > 0) {
        x = min(max(sa[tid - 1], sl[tid - 1]), sh[tid - 1]);  // clip(0 + a, l, h)
    }
#pragma unroll
    for (int i = 0; i < 8; i++) {
        x = min(max(x + d[i], 0), NUM_LEVELS - 1);
        g_levels[b * SEQ + base + i] = (unsigned char)x;
    }
}

// ---------------------------------------------------------------------------
// Kernel B: out[token, :] = scaled_emb[level[token], :]
// Pre-scaled embedding table (32 x 1024 fp32 = 128 KB) lives in dynamic smem,
// so the only LTS/DRAM traffic is the 256 MB of output writes (roofline).
// 148 persistent blocks x 1024 threads. Each block handles 4 tokens per
// iteration: 4 groups of 256 threads, one float4 store per thread.
// ---------------------------------------------------------------------------
__global__ __launch_bounds__(1024) void gather_kernel(const float* __restrict__ emb,
                                                      float4* __restrict__ out) {
    extern __shared__ float semb[];
    const int tid = threadIdx.x;

    // load + scale the table into smem (32768 floats = 8192 float4)
    const float4* __restrict__ e4 = (const float4*)emb;
    float4* s4 = (float4*)semb;
    for (int i = tid; i < NUM_LEVELS * DIM / 4; i += 1024) {
        float4 v = e4[i];
        v.x *= SCALE_F; v.y *= SCALE_F; v.z *= SCALE_F; v.w *= SCALE_F;
        s4[i] = v;
    }
    __syncthreads();

    const int g = tid >> 8;    // token group within block: 0..3
    const int j = tid & 255;   // float4 index within row: 0..255

    for (int base = blockIdx.x * 4; base < NTOK; base += gridDim.x * 4) {
        const int token = base + g;   // NTOK % 4 == 0, so always in range
        const int lvl = (int)g_levels[token];
        const float4 v = s4[lvl * (DIM / 4) + j];
        __stcs(&out[(size_t)token * (DIM / 4) + j], v);  // streaming store
    }
}

extern "C" void kernel_launch(void* const* d_in, const int* in_sizes, int n_in,
                              void* d_out, int out_size) {
    const int* token_ids = (const int*)d_in[0];
    const float* level_emb = (const float*)d_in[1];
    float4* out = (float4*)d_out;

    // 128 KB dynamic smem needs opt-in (idempotent host-side call; not a
    // stream op, safe under graph capture)
    cudaFuncSetAttribute(gather_kernel,
                         cudaFuncAttributeMaxDynamicSharedMemorySize,
                         NUM_LEVELS * DIM * (int)sizeof(float));

    levels_kernel<<<BATCH, 1024>>>(token_ids);
    gather_kernel<<<148, 1024, NUM_LEVELS * DIM * sizeof(float)>>>(level_emb, out);
}